// round 15
// baseline (speedup 1.0000x reference)
#include <cuda_runtime.h>
#include <cuda_fp16.h>
#include <cstdint>

#define NMU 32
#define NMB 4
#define GRIDSZ 128
#define BLOCK 256
#define Tsz 512
#define Hsz 512

// ---- recurrent kernel smem layout ----
#define WPAD 520
#define ZPAD 520
#define R_OFF_W    0
#define R_OFF_Z    66560
#define R_OFF_H    133120
#define R_SMEM     135296

// ---- prep kernel smem layout ----
#define PWPAD 200
#define PZPAD 40
#define P_OFF_WH 0
#define P_OFF_Z  25600
#define P_OFF_B  46080
#define P_SMEM   46336

// h ping-pong image (fp16), [slot][batch][unit]
__device__ unsigned short g_Zh[2][256][512];
// xg[t][mu][row(64)][b(256)] fp32, bias folded
__device__ float g_xg[268435456ull];
// readout partials [slot][mu][mb][mh][b64]
__device__ float g_pout[2][NMU][NMB][2][64];
__device__ unsigned g_bar[NMB];

__device__ __forceinline__ unsigned short cvt1h(float v){
    return __half_as_ushort(__float2half_rn(v));
}
__device__ __forceinline__ float sigf(float x){ return __fdividef(1.0f, 1.0f + __expf(-x)); }

__device__ __forceinline__ void mma16816(float* d, const unsigned* a, const unsigned* b){
    asm volatile("mma.sync.aligned.m16n8k16.row.col.f32.f16.f16.f32 "
        "{%0,%1,%2,%3}, {%4,%5,%6,%7}, {%8,%9}, {%0,%1,%2,%3};"
        : "+f"(d[0]), "+f"(d[1]), "+f"(d[2]), "+f"(d[3])
        : "r"(a[0]), "r"(a[1]), "r"(a[2]), "r"(a[3]), "r"(b[0]), "r"(b[1]));
}
__device__ __forceinline__ void ldsm_x4(unsigned* r, uint32_t addr){
    asm volatile("ldmatrix.sync.aligned.m8n8.x4.shared.b16 {%0,%1,%2,%3}, [%4];"
        : "=r"(r[0]), "=r"(r[1]), "=r"(r[2]), "=r"(r[3]) : "r"(addr));
}
__device__ __forceinline__ uint32_t smem_u32(const void* p){
    uint32_t a; asm("{ .reg .u64 t; cvta.to.shared.u64 t, %1; cvt.u32.u64 %0, t; }" : "=r"(a) : "l"(p));
    return a;
}
__device__ __forceinline__ void cp_async16(uint32_t dst, const void* src){
    asm volatile("cp.async.cg.shared.global [%0], [%1], 16;" :: "r"(dst), "l"(src));
}
__device__ __forceinline__ void cp_commit_wait(){
    asm volatile("cp.async.commit_group;\ncp.async.wait_group 0;" ::: "memory");
}
__device__ __forceinline__ void bar_arrive(unsigned* p){
    asm volatile("red.release.gpu.global.add.u32 [%0], %1;" :: "l"(p), "r"(1u) : "memory");
}
__device__ __forceinline__ unsigned bar_ld(const unsigned* p){
    unsigned v;
    asm volatile("ld.acquire.gpu.global.u32 %0, [%1];" : "=r"(v) : "l"(p) : "memory");
    return v;
}

// ---- pad: profile-slot alignment only ----
__global__ void pad_kernel() {}

// ---- init: reset barriers + h0 -> slot-1 fp16 image ----
__global__ void init_kernel(const float* __restrict__ h0){
    if (blockIdx.x == 0 && threadIdx.x < NMB) g_bar[threadIdx.x] = 0u;
    const int b = blockIdx.x;
    const int j = threadIdx.x * 4;
#pragma unroll
    for (int e = 0; e < 4; ++e)
        g_Zh[1][b][j + e] = cvt1h(h0[(size_t)b * Hsz + j + e]);
}

// ---- prep: xg[t][mu][row][b] = W_ih(R).x(b,t) + b_ih + b_hh  (single-term fp16) ----
__global__ void __launch_bounds__(256, 1) prep_xg_kernel(
    const float* __restrict__ obs, const float* __restrict__ act,
    const float* __restrict__ W_ih,
    const float* __restrict__ b_ih, const float* __restrict__ b_hh)
{
    extern __shared__ unsigned char sm8[];
    unsigned short* WH = (unsigned short*)(sm8 + P_OFF_WH);
    unsigned short* ZH = (unsigned short*)(sm8 + P_OFF_Z);
    float* bias = (float*)(sm8 + P_OFF_B);

    const int tid = threadIdx.x;
    const int wid = tid >> 5, lane = tid & 31, grp = lane >> 2, qid = lane & 3;
    const int tgB = blockIdx.x >> 7;
    const int mu = (blockIdx.x >> 2) & 31;
    const int mb = blockIdx.x & 3;
    const int mh = wid >> 2;
    const int nh = wid & 3;

    {
        const int r = tid >> 2, l4 = tid & 3;
        const int R = (r & 3) * Hsz + mu * 16 + (r >> 2);
        for (int k = l4; k < 192; k += 4)
            WH[r * PWPAD + k] = cvt1h(W_ih[(size_t)R * 192 + k]);
    }
    if (tid < 64) {
        int R = (tid & 3) * Hsz + mu * 16 + (tid >> 2);
        bias[tid] = b_ih[R] + b_hh[R];
    }
    __syncthreads();

    const int bg = mb * 64 + (tid & 63);

    for (int tg = 0; tg < 4; ++tg) {
        const int t0 = tgB * 16 + tg * 4;
        const int tt = t0 + (tid >> 6);
        const float* xrow_obs = obs + ((size_t)bg * Tsz + tt) * 128;
        const float* xrow_act = act + ((size_t)bg * Tsz + tt) * 64;

        float acc[2][8][4];
#pragma unroll
        for (int mt = 0; mt < 2; ++mt)
#pragma unroll
            for (int nt = 0; nt < 8; ++nt)
#pragma unroll
                for (int j = 0; j < 4; ++j) acc[mt][nt][j] = 0.f;

        float4 pf[8];
        {
            const float4* s = (const float4*)xrow_obs;
#pragma unroll
            for (int j = 0; j < 8; ++j) pf[j] = s[j];
        }

        for (int blk = 0; blk < 6; ++blk) {
            __syncthreads();
            {
                unsigned short* dst = ZH + tid * PZPAD;
                const float* f = (const float*)pf;
                union { unsigned short s[8]; uint4 v; } u;
#pragma unroll
                for (int g4 = 0; g4 < 4; ++g4) {
#pragma unroll
                    for (int j = 0; j < 8; ++j) u.s[j] = cvt1h(f[g4 * 8 + j]);
                    *(uint4*)(dst + g4 * 8) = u.v;
                }
            }
            __syncthreads();
            if (blk + 1 < 6) {
                const int nb = blk + 1;
                const float4* s = (nb < 4) ? (const float4*)(xrow_obs + nb * 32)
                                           : (const float4*)(xrow_act + (nb - 4) * 32);
#pragma unroll
                for (int j = 0; j < 8; ++j) pf[j] = s[j];
            }
#pragma unroll
            for (int ks = 0; ks < 2; ++ks) {
                const int kw = blk * 32 + ks * 16 + qid * 2;
                const int kz = ks * 16 + qid * 2;
                unsigned aH[2][4], bF[8][2];
#pragma unroll
                for (int mt = 0; mt < 2; ++mt) {
                    const int r0 = (mh * 32 + mt * 16 + grp) * PWPAD;
                    aH[mt][0] = *(const unsigned*)&WH[r0 + kw];
                    aH[mt][1] = *(const unsigned*)&WH[r0 + 8 * PWPAD + kw];
                    aH[mt][2] = *(const unsigned*)&WH[r0 + kw + 8];
                    aH[mt][3] = *(const unsigned*)&WH[r0 + 8 * PWPAD + kw + 8];
                }
#pragma unroll
                for (int nt = 0; nt < 8; ++nt) {
                    const int n0 = (nh * 64 + nt * 8 + grp) * PZPAD;
                    bF[nt][0] = *(const unsigned*)&ZH[n0 + kz];
                    bF[nt][1] = *(const unsigned*)&ZH[n0 + kz + 8];
                }
#pragma unroll
                for (int mt = 0; mt < 2; ++mt)
#pragma unroll
                    for (int nt = 0; nt < 8; ++nt)
                        mma16816(acc[mt][nt], aH[mt], bF[nt]);
            }
        }

        const int tcol = t0 + nh;
        const size_t base = (size_t)(tcol * 32 + mu) * 16384 + (size_t)mb * 64;
#pragma unroll
        for (int mt = 0; mt < 2; ++mt)
#pragma unroll
            for (int nt = 0; nt < 8; ++nt) {
                const int row = mh * 32 + mt * 16 + grp;
                const int bcol = nt * 8 + qid * 2;
                float2 v0 = make_float2(acc[mt][nt][0] + bias[row],
                                        acc[mt][nt][1] + bias[row]);
                float2 v1 = make_float2(acc[mt][nt][2] + bias[row + 8],
                                        acc[mt][nt][3] + bias[row + 8]);
                *(float2*)&g_xg[base + (size_t)row * 256 + bcol] = v0;
                *(float2*)&g_xg[base + (size_t)(row + 8) * 256 + bcol] = v1;
            }
        __syncthreads();
    }
}

// ---- recurrent: register-transpose epilogue, packed h publication ----
__global__ void __launch_bounds__(BLOCK, 1) lstm_hmma_kernel(
    const float* __restrict__ c0,
    const float* __restrict__ W_hh,
    const float* __restrict__ W_out, const float* __restrict__ b_out,
    float* __restrict__ out)
{
    extern __shared__ unsigned char sm8[];
    unsigned short* WH = (unsigned short*)(sm8 + R_OFF_W);
    unsigned short* Z0 = (unsigned short*)(sm8 + R_OFF_Z);
    unsigned short* hsm = (unsigned short*)(sm8 + R_OFF_H);   // [64 batch][16 unit]

    const int tid = threadIdx.x;
    const int wid = tid >> 5, lane = tid & 31, qid = lane & 3;
    const int mu = blockIdx.x >> 2, mb = blockIdx.x & 3;
    const int mh = wid >> 2;            // M half (32 rows)
    const int nq = wid & 3;             // N quarter (16 cols)
    const int aA = (lane >> 2) & 3;
    const int b3 = lane >> 4;

    // ---- init: W_hh fp16 ----
    {
        const int r = tid >> 2, l4 = tid & 3;
        const int R = (r & 3) * Hsz + mu * 16 + (r >> 2);
        for (int k = l4; k < 512; k += 4)
            WH[r * WPAD + k] = cvt1h(W_hh[(size_t)R * Hsz + k]);
    }

    // per-lane (U, C) assignment
    int Uc[2], Cc[2];
#pragma unroll
    for (int mt = 0; mt < 2; ++mt) Uc[mt] = mh * 8 + mt * 4 + (aA >> 1) * 2 + b3;
#pragma unroll
    for (int nt = 0; nt < 2; ++nt) Cc[nt] = nq * 16 + nt * 8 + qid * 2 + (aA & 1);

    float cR[2][2], woutR[2];
#pragma unroll
    for (int mt = 0; mt < 2; ++mt) {
        woutR[mt] = W_out[mu * 16 + Uc[mt]];
#pragma unroll
        for (int nt = 0; nt < 2; ++nt)
            cR[mt][nt] = c0[(size_t)(mb * 64 + Cc[nt]) * Hsz + mu * 16 + Uc[mt]];
    }
    __syncthreads();

    const float bout = b_out[0];

    // ldmatrix per-lane addresses
    const int lrow = lane & 7, lgrp = lane >> 3;
    uint32_t aAddr[2];
#pragma unroll
    for (int mt = 0; mt < 2; ++mt) {
        const int row = mh * 32 + mt * 16 + (lgrp & 1) * 8 + lrow;
        aAddr[mt] = smem_u32(WH) + (uint32_t)(row * WPAD + (lgrp >> 1) * 8) * 2;
    }
    const uint32_t bAddr = smem_u32(Z0)
        + (uint32_t)((nq * 16 + (lgrp >> 1) * 8 + lrow) * ZPAD + (lgrp & 1) * 8) * 2;

    // staging mapping
    const int zr = tid & 63, zq = tid >> 6;
    const int bg = mb * 64 + zr;
    const uint32_t zdst = smem_u32(Z0) + (uint32_t)(zr * ZPAD) * 2;

    // xg per-lane offsets
    int xoff[2][2];
#pragma unroll
    for (int mt = 0; mt < 2; ++mt)
#pragma unroll
        for (int nt = 0; nt < 2; ++nt)
            xoff[mt][nt] = (Uc[mt] * 4) * 256 + mb * 64 + Cc[nt];

    for (int t = 0; t < Tsz; ++t) {
        const int slotR = (t + 1) & 1, slotW = t & 1;

        // ---- xg prefetch (hidden under spin) ----
        float xgr[2][2][4];
        {
            const float* p = g_xg + (size_t)t * 524288 + (size_t)mu * 16384;
#pragma unroll
            for (int mt = 0; mt < 2; ++mt)
#pragma unroll
                for (int nt = 0; nt < 2; ++nt)
#pragma unroll
                    for (int g = 0; g < 4; ++g)
                        xgr[mt][nt][g] = __ldcg(p + xoff[mt][nt] + g * 256);
        }

        // ---- wait for h(t-1): single-thread poll (4 arrivals/CTA/step) ----
        if (t > 0 && tid == 0)
            while (bar_ld(&g_bar[mb]) < 128u * (unsigned)t) { }
        __syncthreads();

        // ---- one-shot Z staging via cp.async ----
        {
            const unsigned short* srow = &g_Zh[slotR][bg][0];
#pragma unroll
            for (int j = 0; j < 16; ++j) {
                const int g = zq + 4 * j;
                cp_async16(zdst + (uint32_t)(g * 16), srow + g * 8);
            }
        }

        // ---- readout of step t-1 in the staging shadow ----
        if (t > 0 && wid < 2) {
            const int bl = mu * 2 + wid;
            float v = 0.f;
#pragma unroll
            for (int j = 0; j < 2; ++j)
                v += __ldcg(&g_pout[slotR][lane][mb][j][bl]);
#pragma unroll
            for (int off = 16; off; off >>= 1)
                v += __shfl_down_sync(0xffffffffu, v, off);
            if (lane == 0)
                out[(size_t)(mb * 64 + bl) * Tsz + (t - 1)] = v + bout;
        }

        cp_commit_wait();
        __syncthreads();

        // ---- zero-sync MMA mainloop: 32 k-slices ----
        float acc[2][2][4];
#pragma unroll
        for (int mt = 0; mt < 2; ++mt)
#pragma unroll
            for (int nt = 0; nt < 2; ++nt)
#pragma unroll
                for (int j = 0; j < 4; ++j) acc[mt][nt][j] = 0.f;

#pragma unroll
        for (int sl = 0; sl < 32; ++sl) {
            const uint32_t ko = (uint32_t)(sl * 16 * 2);
            unsigned A0[4], A1[4], Bv[4];
            ldsm_x4(A0, aAddr[0] + ko);
            ldsm_x4(A1, aAddr[1] + ko);
            ldsm_x4(Bv, bAddr + ko);
            mma16816(acc[0][0], A0, Bv);
            mma16816(acc[0][1], A0, Bv + 2);
            mma16816(acc[1][0], A1, Bv);
            mma16816(acc[1][1], A1, Bv + 2);
        }

        // ---- register transpose + cell update ----
        float hn[2][2];
        const bool hiA = (lane & 4) != 0;
        const bool hiB = (lane & 8) != 0;
#pragma unroll
        for (int mt = 0; mt < 2; ++mt)
#pragma unroll
            for (int nt = 0; nt < 2; ++nt) {
                float v0 = acc[mt][nt][0], v1 = acc[mt][nt][1];
                float v2 = acc[mt][nt][2], v3 = acc[mt][nt][3];
                float s, r;
                s = hiA ? v0 : v1; r = __shfl_xor_sync(0xffffffffu, s, 4);
                if (hiA) v0 = r; else v1 = r;
                s = hiA ? v2 : v3; r = __shfl_xor_sync(0xffffffffu, s, 4);
                if (hiA) v2 = r; else v3 = r;
                s = hiB ? v0 : v2; r = __shfl_xor_sync(0xffffffffu, s, 8);
                if (hiB) v0 = r; else v2 = r;
                s = hiB ? v1 : v3; r = __shfl_xor_sync(0xffffffffu, s, 8);
                if (hiB) v1 = r; else v3 = r;
                float iv = sigf(v0 + xgr[mt][nt][0]);
                float fv = sigf(v1 + xgr[mt][nt][1]);
                float gv = tanhf(v2 + xgr[mt][nt][2]);
                float ov = sigf(v3 + xgr[mt][nt][3]);
                float cn = fv * cR[mt][nt] + iv * gv;
                cR[mt][nt] = cn;
                float h = ov * tanhf(cn);
                hn[mt][nt] = h;
                hsm[Cc[nt] * 16 + Uc[mt]] = cvt1h(h);   // smem bounce (no global scatter)
            }

        // ---- readout partials: shfl-reduce over 8 units ----
        {
            float p0 = woutR[0] * hn[0][0] + woutR[1] * hn[1][0];
            float p1 = woutR[0] * hn[0][1] + woutR[1] * hn[1][1];
            p0 += __shfl_xor_sync(0xffffffffu, p0, 8);
            p0 += __shfl_xor_sync(0xffffffffu, p0, 16);
            p1 += __shfl_xor_sync(0xffffffffu, p1, 8);
            p1 += __shfl_xor_sync(0xffffffffu, p1, 16);
            if ((lane & 24) == 0) {
                g_pout[slotW][mu][mb][mh][Cc[0]] = p0;
                g_pout[slotW][mu][mb][mh][Cc[1]] = p1;
            }
        }

        __syncthreads();   // hsm complete; Z0 reads done; pout ordered

        // ---- packed h publication + distributed arrival (warps 0-3) ----
        if (tid < 128) {
            const int b = tid >> 1, half = tid & 1;
            uint4 v = *(uint4*)&hsm[b * 16 + half * 8];
            *(uint4*)&g_Zh[slotW][mb * 64 + b][mu * 16 + half * 8] = v;
            __syncwarp();
            if ((tid & 31) == 0) bar_arrive(&g_bar[mb]);
        }
    }

    // ---- final readout (t = Tsz-1) ----
    if (tid == 0)
        while (bar_ld(&g_bar[mb]) < 128u * (unsigned)Tsz) { }
    __syncthreads();
    if (wid < 2) {
        const int bl = mu * 2 + wid;
        float v = 0.f;
#pragma unroll
        for (int j = 0; j < 2; ++j)
            v += __ldcg(&g_pout[(Tsz - 1) & 1][lane][mb][j][bl]);
#pragma unroll
        for (int off = 16; off; off >>= 1)
            v += __shfl_down_sync(0xffffffffu, v, off);
        if (lane == 0)
            out[(size_t)(mb * 64 + bl) * Tsz + (Tsz - 1)] = v + bout;
    }
}

extern "C" void kernel_launch(void* const* d_in, const int* in_sizes, int n_in,
                              void* d_out, int out_size)
{
    (void)in_sizes; (void)n_in; (void)out_size;
    cudaFuncSetAttribute(prep_xg_kernel, cudaFuncAttributeMaxDynamicSharedMemorySize, P_SMEM);
    cudaFuncSetAttribute(lstm_hmma_kernel, cudaFuncAttributeMaxDynamicSharedMemorySize, R_SMEM);

    pad_kernel<<<1, 32>>>();                         // keep ncu on the lstm kernel
    init_kernel<<<256, 128>>>((const float*)d_in[2]);
    prep_xg_kernel<<<4096, 256, P_SMEM>>>(
        (const float*)d_in[0],  // observation
        (const float*)d_in[1],  // action
        (const float*)d_in[4],  // W_ih
        (const float*)d_in[6],  // b_ih
        (const float*)d_in[7]); // b_hh
    lstm_hmma_kernel<<<GRIDSZ, BLOCK, R_SMEM>>>(
        (const float*)d_in[3],  // c0
        (const float*)d_in[5],  // W_hh
        (const float*)d_in[8],  // W_out
        (const float*)d_in[9],  // b_out
        (float*)d_out);
}

// round 16
// speedup vs baseline: 1.0396x; 1.0396x over previous
#include <cuda_runtime.h>
#include <cuda_fp16.h>
#include <cstdint>

#define NMU 32
#define NMB 4
#define GRIDSZ 128
#define BLOCK 256
#define Tsz 512
#define Hsz 512

// ---- recurrent kernel smem layout ----
#define WPAD 520
#define ZPAD 520
#define R_OFF_W    0
#define R_OFF_Z    66560
#define R_SMEM     133248

// ---- prep kernel smem layout (single-term) ----
#define PWPAD 200
#define PZPAD 40
#define P_OFF_WH 0
#define P_OFF_Z  25600
#define P_OFF_B  46080
#define P_SMEM   46336

// h ping-pong image (fp16), [slot][batch][unit]
__device__ unsigned short g_Zh[2][256][512];
// xg[t][mu][row(64)][b(256)] fp32, bias folded
__device__ float g_xg[268435456ull];
// readout partials [slot][mu][mb][mh][b64]
__device__ float g_pout[2][NMU][NMB][2][64];
__device__ unsigned g_bar[NMB];

__device__ __forceinline__ unsigned short cvt1h(float v){
    return __half_as_ushort(__float2half_rn(v));
}
__device__ __forceinline__ float sigf(float x){ return __fdividef(1.0f, 1.0f + __expf(-x)); }

__device__ __forceinline__ void mma16816(float* d, const unsigned* a, const unsigned* b){
    asm volatile("mma.sync.aligned.m16n8k16.row.col.f32.f16.f16.f32 "
        "{%0,%1,%2,%3}, {%4,%5,%6,%7}, {%8,%9}, {%0,%1,%2,%3};"
        : "+f"(d[0]), "+f"(d[1]), "+f"(d[2]), "+f"(d[3])
        : "r"(a[0]), "r"(a[1]), "r"(a[2]), "r"(a[3]), "r"(b[0]), "r"(b[1]));
}
__device__ __forceinline__ void ldsm_x4(unsigned* r, uint32_t addr){
    asm volatile("ldmatrix.sync.aligned.m8n8.x4.shared.b16 {%0,%1,%2,%3}, [%4];"
        : "=r"(r[0]), "=r"(r[1]), "=r"(r[2]), "=r"(r[3]) : "r"(addr));
}
__device__ __forceinline__ uint32_t smem_u32(const void* p){
    uint32_t a; asm("{ .reg .u64 t; cvta.to.shared.u64 t, %1; cvt.u32.u64 %0, t; }" : "=r"(a) : "l"(p));
    return a;
}
__device__ __forceinline__ void cp_async16(uint32_t dst, const void* src){
    asm volatile("cp.async.cg.shared.global [%0], [%1], 16;" :: "r"(dst), "l"(src));
}
__device__ __forceinline__ void cp_commit_wait(){
    asm volatile("cp.async.commit_group;\ncp.async.wait_group 0;" ::: "memory");
}
__device__ __forceinline__ void bar_arrive(unsigned* p){
    asm volatile("red.release.gpu.global.add.u32 [%0], %1;" :: "l"(p), "r"(1u) : "memory");
}
__device__ __forceinline__ unsigned bar_ld(const unsigned* p){
    unsigned v;
    asm volatile("ld.acquire.gpu.global.u32 %0, [%1];" : "=r"(v) : "l"(p) : "memory");
    return v;
}

// ---- pad: profile-slot alignment only ----
__global__ void pad_kernel() {}

// ---- init: reset barriers + h0 -> slot-1 fp16 image ----
__global__ void init_kernel(const float* __restrict__ h0){
    if (blockIdx.x == 0 && threadIdx.x < NMB) g_bar[threadIdx.x] = 0u;
    const int b = blockIdx.x;
    const int j = threadIdx.x * 4;
#pragma unroll
    for (int e = 0; e < 4; ++e)
        g_Zh[1][b][j + e] = cvt1h(h0[(size_t)b * Hsz + j + e]);
}

// ---- prep: xg[t][mu][row][b] = W_ih(R).x(b,t) + b_ih + b_hh  (single-term fp16) ----
__global__ void __launch_bounds__(256, 1) prep_xg_kernel(
    const float* __restrict__ obs, const float* __restrict__ act,
    const float* __restrict__ W_ih,
    const float* __restrict__ b_ih, const float* __restrict__ b_hh)
{
    extern __shared__ unsigned char sm8[];
    unsigned short* WH = (unsigned short*)(sm8 + P_OFF_WH);
    unsigned short* ZH = (unsigned short*)(sm8 + P_OFF_Z);
    float* bias = (float*)(sm8 + P_OFF_B);

    const int tid = threadIdx.x;
    const int wid = tid >> 5, lane = tid & 31, grp = lane >> 2, qid = lane & 3;
    const int tgB = blockIdx.x >> 7;
    const int mu = (blockIdx.x >> 2) & 31;
    const int mb = blockIdx.x & 3;
    const int mh = wid >> 2;
    const int nh = wid & 3;

    {
        const int r = tid >> 2, l4 = tid & 3;
        const int R = (r & 3) * Hsz + mu * 16 + (r >> 2);
        for (int k = l4; k < 192; k += 4)
            WH[r * PWPAD + k] = cvt1h(W_ih[(size_t)R * 192 + k]);
    }
    if (tid < 64) {
        int R = (tid & 3) * Hsz + mu * 16 + (tid >> 2);
        bias[tid] = b_ih[R] + b_hh[R];
    }
    __syncthreads();

    const int bg = mb * 64 + (tid & 63);

    for (int tg = 0; tg < 4; ++tg) {
        const int t0 = tgB * 16 + tg * 4;
        const int tt = t0 + (tid >> 6);
        const float* xrow_obs = obs + ((size_t)bg * Tsz + tt) * 128;
        const float* xrow_act = act + ((size_t)bg * Tsz + tt) * 64;

        float acc[2][8][4];
#pragma unroll
        for (int mt = 0; mt < 2; ++mt)
#pragma unroll
            for (int nt = 0; nt < 8; ++nt)
#pragma unroll
                for (int j = 0; j < 4; ++j) acc[mt][nt][j] = 0.f;

        float4 pf[8];
        {
            const float4* s = (const float4*)xrow_obs;
#pragma unroll
            for (int j = 0; j < 8; ++j) pf[j] = s[j];
        }

        for (int blk = 0; blk < 6; ++blk) {
            __syncthreads();
            {
                unsigned short* dst = ZH + tid * PZPAD;
                const float* f = (const float*)pf;
                union { unsigned short s[8]; uint4 v; } u;
#pragma unroll
                for (int g4 = 0; g4 < 4; ++g4) {
#pragma unroll
                    for (int j = 0; j < 8; ++j) u.s[j] = cvt1h(f[g4 * 8 + j]);
                    *(uint4*)(dst + g4 * 8) = u.v;
                }
            }
            __syncthreads();
            if (blk + 1 < 6) {
                const int nb = blk + 1;
                const float4* s = (nb < 4) ? (const float4*)(xrow_obs + nb * 32)
                                           : (const float4*)(xrow_act + (nb - 4) * 32);
#pragma unroll
                for (int j = 0; j < 8; ++j) pf[j] = s[j];
            }
#pragma unroll
            for (int ks = 0; ks < 2; ++ks) {
                const int kw = blk * 32 + ks * 16 + qid * 2;
                const int kz = ks * 16 + qid * 2;
                unsigned aH[2][4], bF[8][2];
#pragma unroll
                for (int mt = 0; mt < 2; ++mt) {
                    const int r0 = (mh * 32 + mt * 16 + grp) * PWPAD;
                    aH[mt][0] = *(const unsigned*)&WH[r0 + kw];
                    aH[mt][1] = *(const unsigned*)&WH[r0 + 8 * PWPAD + kw];
                    aH[mt][2] = *(const unsigned*)&WH[r0 + kw + 8];
                    aH[mt][3] = *(const unsigned*)&WH[r0 + 8 * PWPAD + kw + 8];
                }
#pragma unroll
                for (int nt = 0; nt < 8; ++nt) {
                    const int n0 = (nh * 64 + nt * 8 + grp) * PZPAD;
                    bF[nt][0] = *(const unsigned*)&ZH[n0 + kz];
                    bF[nt][1] = *(const unsigned*)&ZH[n0 + kz + 8];
                }
#pragma unroll
                for (int mt = 0; mt < 2; ++mt)
#pragma unroll
                    for (int nt = 0; nt < 8; ++nt)
                        mma16816(acc[mt][nt], aH[mt], bF[nt]);
            }
        }

        const int tcol = t0 + nh;
        const size_t base = (size_t)(tcol * 32 + mu) * 16384 + (size_t)mb * 64;
#pragma unroll
        for (int mt = 0; mt < 2; ++mt)
#pragma unroll
            for (int nt = 0; nt < 8; ++nt) {
                const int row = mh * 32 + mt * 16 + grp;
                const int bcol = nt * 8 + qid * 2;
                float2 v0 = make_float2(acc[mt][nt][0] + bias[row],
                                        acc[mt][nt][1] + bias[row]);
                float2 v1 = make_float2(acc[mt][nt][2] + bias[row + 8],
                                        acc[mt][nt][3] + bias[row + 8]);
                *(float2*)&g_xg[base + (size_t)row * 256 + bcol] = v0;
                *(float2*)&g_xg[base + (size_t)(row + 8) * 256 + bcol] = v1;
            }
        __syncthreads();
    }
}

// ---- recurrent: R14 verbatim (register-transpose epilogue, c in registers) ----
__global__ void __launch_bounds__(BLOCK, 1) lstm_hmma_kernel(
    const float* __restrict__ c0,
    const float* __restrict__ W_hh,
    const float* __restrict__ W_out, const float* __restrict__ b_out,
    float* __restrict__ out)
{
    extern __shared__ unsigned char sm8[];
    unsigned short* WH = (unsigned short*)(sm8 + R_OFF_W);
    unsigned short* Z0 = (unsigned short*)(sm8 + R_OFF_Z);

    const int tid = threadIdx.x;
    const int wid = tid >> 5, lane = tid & 31, qid = lane & 3;
    const int mu = blockIdx.x >> 2, mb = blockIdx.x & 3;
    const int mh = wid >> 2;            // M half (32 rows)
    const int nq = wid & 3;             // N quarter (16 cols)
    const int aA = (lane >> 2) & 3;
    const int b3 = lane >> 4;

    // ---- init: W_hh fp16 ----
    {
        const int r = tid >> 2, l4 = tid & 3;
        const int R = (r & 3) * Hsz + mu * 16 + (r >> 2);
        for (int k = l4; k < 512; k += 4)
            WH[r * WPAD + k] = cvt1h(W_hh[(size_t)R * Hsz + k]);
    }

    // per-lane (U, C) assignment
    int Uc[2], Cc[2];
#pragma unroll
    for (int mt = 0; mt < 2; ++mt) Uc[mt] = mh * 8 + mt * 4 + (aA >> 1) * 2 + b3;
#pragma unroll
    for (int nt = 0; nt < 2; ++nt) Cc[nt] = nq * 16 + nt * 8 + qid * 2 + (aA & 1);

    float cR[2][2], woutR[2];
#pragma unroll
    for (int mt = 0; mt < 2; ++mt) {
        woutR[mt] = W_out[mu * 16 + Uc[mt]];
#pragma unroll
        for (int nt = 0; nt < 2; ++nt)
            cR[mt][nt] = c0[(size_t)(mb * 64 + Cc[nt]) * Hsz + mu * 16 + Uc[mt]];
    }
    __syncthreads();

    const float bout = b_out[0];

    // ldmatrix per-lane addresses
    const int lrow = lane & 7, lgrp = lane >> 3;
    uint32_t aAddr[2];
#pragma unroll
    for (int mt = 0; mt < 2; ++mt) {
        const int row = mh * 32 + mt * 16 + (lgrp & 1) * 8 + lrow;
        aAddr[mt] = smem_u32(WH) + (uint32_t)(row * WPAD + (lgrp >> 1) * 8) * 2;
    }
    const uint32_t bAddr = smem_u32(Z0)
        + (uint32_t)((nq * 16 + (lgrp >> 1) * 8 + lrow) * ZPAD + (lgrp & 1) * 8) * 2;

    // staging mapping
    const int zr = tid & 63, zq = tid >> 6;
    const int bg = mb * 64 + zr;
    const uint32_t zdst = smem_u32(Z0) + (uint32_t)(zr * ZPAD) * 2;

    // xg per-lane offsets
    int xoff[2][2];
#pragma unroll
    for (int mt = 0; mt < 2; ++mt)
#pragma unroll
        for (int nt = 0; nt < 2; ++nt)
            xoff[mt][nt] = (Uc[mt] * 4) * 256 + mb * 64 + Cc[nt];

    for (int t = 0; t < Tsz; ++t) {
        const int slotR = (t + 1) & 1, slotW = t & 1;

        // ---- xg prefetch (hidden under spin) ----
        float xgr[2][2][4];
        {
            const float* p = g_xg + (size_t)t * 524288 + (size_t)mu * 16384;
#pragma unroll
            for (int mt = 0; mt < 2; ++mt)
#pragma unroll
                for (int nt = 0; nt < 2; ++nt)
#pragma unroll
                    for (int g = 0; g < 4; ++g)
                        xgr[mt][nt][g] = __ldcg(p + xoff[mt][nt] + g * 256);
        }

        // ---- wait for h(t-1): single-thread poll ----
        if (t > 0 && tid == 0)
            while (bar_ld(&g_bar[mb]) < 32u * (unsigned)t) { }
        __syncthreads();

        // ---- one-shot Z staging via cp.async ----
        {
            const unsigned short* srow = &g_Zh[slotR][bg][0];
#pragma unroll
            for (int j = 0; j < 16; ++j) {
                const int g = zq + 4 * j;
                cp_async16(zdst + (uint32_t)(g * 16), srow + g * 8);
            }
        }

        // ---- readout of step t-1 in the staging shadow ----
        if (t > 0 && wid < 2) {
            const int bl = mu * 2 + wid;
            float v = 0.f;
#pragma unroll
            for (int j = 0; j < 2; ++j)
                v += __ldcg(&g_pout[slotR][lane][mb][j][bl]);
#pragma unroll
            for (int off = 16; off; off >>= 1)
                v += __shfl_down_sync(0xffffffffu, v, off);
            if (lane == 0)
                out[(size_t)(mb * 64 + bl) * Tsz + (t - 1)] = v + bout;
        }

        cp_commit_wait();
        __syncthreads();

        // ---- zero-sync MMA mainloop: 32 k-slices ----
        float acc[2][2][4];
#pragma unroll
        for (int mt = 0; mt < 2; ++mt)
#pragma unroll
            for (int nt = 0; nt < 2; ++nt)
#pragma unroll
                for (int j = 0; j < 4; ++j) acc[mt][nt][j] = 0.f;

#pragma unroll
        for (int sl = 0; sl < 32; ++sl) {
            const uint32_t ko = (uint32_t)(sl * 16 * 2);
            unsigned A0[4], A1[4], Bv[4];
            ldsm_x4(A0, aAddr[0] + ko);
            ldsm_x4(A1, aAddr[1] + ko);
            ldsm_x4(Bv, bAddr + ko);
            mma16816(acc[0][0], A0, Bv);
            mma16816(acc[0][1], A0, Bv + 2);
            mma16816(acc[1][0], A1, Bv);
            mma16816(acc[1][1], A1, Bv + 2);
        }

        // ---- register transpose + cell update (no smem, no sync) ----
        float hn[2][2];
        const bool hiA = (lane & 4) != 0;
        const bool hiB = (lane & 8) != 0;
#pragma unroll
        for (int mt = 0; mt < 2; ++mt)
#pragma unroll
            for (int nt = 0; nt < 2; ++nt) {
                float v0 = acc[mt][nt][0], v1 = acc[mt][nt][1];
                float v2 = acc[mt][nt][2], v3 = acc[mt][nt][3];
                float s, r;
                s = hiA ? v0 : v1; r = __shfl_xor_sync(0xffffffffu, s, 4);
                if (hiA) v0 = r; else v1 = r;
                s = hiA ? v2 : v3; r = __shfl_xor_sync(0xffffffffu, s, 4);
                if (hiA) v2 = r; else v3 = r;
                s = hiB ? v0 : v2; r = __shfl_xor_sync(0xffffffffu, s, 8);
                if (hiB) v0 = r; else v2 = r;
                s = hiB ? v1 : v3; r = __shfl_xor_sync(0xffffffffu, s, 8);
                if (hiB) v1 = r; else v3 = r;
                float iv = sigf(v0 + xgr[mt][nt][0]);
                float fv = sigf(v1 + xgr[mt][nt][1]);
                float gv = tanhf(v2 + xgr[mt][nt][2]);
                float ov = sigf(v3 + xgr[mt][nt][3]);
                float cn = fv * cR[mt][nt] + iv * gv;
                cR[mt][nt] = cn;
                float h = ov * tanhf(cn);
                hn[mt][nt] = h;
                g_Zh[slotW][mb * 64 + Cc[nt]][mu * 16 + Uc[mt]] = cvt1h(h);
            }

        // ---- readout partials: shfl-reduce over 8 units ----
        {
            float p0 = woutR[0] * hn[0][0] + woutR[1] * hn[1][0];
            float p1 = woutR[0] * hn[0][1] + woutR[1] * hn[1][1];
            p0 += __shfl_xor_sync(0xffffffffu, p0, 8);
            p0 += __shfl_xor_sync(0xffffffffu, p0, 16);
            p1 += __shfl_xor_sync(0xffffffffu, p1, 8);
            p1 += __shfl_xor_sync(0xffffffffu, p1, 16);
            if ((lane & 24) == 0) {
                g_pout[slotW][mu][mb][mh][Cc[0]] = p0;
                g_pout[slotW][mu][mb][mh][Cc[1]] = p1;
            }
        }

        __syncthreads();                       // Z0 reads done; h/pout ordered
        if (tid == 0) bar_arrive(&g_bar[mb]);
    }

    // ---- final readout (t = Tsz-1) ----
    if (tid == 0)
        while (bar_ld(&g_bar[mb]) < 32u * (unsigned)Tsz) { }
    __syncthreads();
    if (wid < 2) {
        const int bl = mu * 2 + wid;
        float v = 0.f;
#pragma unroll
        for (int j = 0; j < 2; ++j)
            v += __ldcg(&g_pout[(Tsz - 1) & 1][lane][mb][j][bl]);
#pragma unroll
        for (int off = 16; off; off >>= 1)
            v += __shfl_down_sync(0xffffffffu, v, off);
        if (lane == 0)
            out[(size_t)(mb * 64 + bl) * Tsz + (Tsz - 1)] = v + bout;
    }
}

extern "C" void kernel_launch(void* const* d_in, const int* in_sizes, int n_in,
                              void* d_out, int out_size)
{
    (void)in_sizes; (void)n_in; (void)out_size;
    cudaFuncSetAttribute(prep_xg_kernel, cudaFuncAttributeMaxDynamicSharedMemorySize, P_SMEM);
    cudaFuncSetAttribute(lstm_hmma_kernel, cudaFuncAttributeMaxDynamicSharedMemorySize, R_SMEM);

    pad_kernel<<<1, 32>>>();                         // keep ncu on the lstm kernel
    init_kernel<<<256, 128>>>((const float*)d_in[2]);
    prep_xg_kernel<<<4096, 256, P_SMEM>>>(
        (const float*)d_in[0],  // observation
        (const float*)d_in[1],  // action
        (const float*)d_in[4],  // W_ih
        (const float*)d_in[6],  // b_ih
        (const float*)d_in[7]); // b_hh
    lstm_hmma_kernel<<<GRIDSZ, BLOCK, R_SMEM>>>(
        (const float*)d_in[3],  // c0
        (const float*)d_in[5],  // W_hh
        (const float*)d_in[8],  // W_out
        (const float*)d_in[9],  // b_out
        (float*)d_out);
}